// round 1
// baseline (speedup 1.0000x reference)
#include <cuda_runtime.h>
#include <cmath>

#define HDIM 768
#define TSEQ 2048
#define BATCH 4
#define MT (BATCH * TSEQ)   // 8192 total rows

// ---------------- scratch (allocation-free: __device__ globals) ----------------
__device__ float g_x[MT * HDIM];            // layernorm output
__device__ float g_U[MT * HDIM];
__device__ float g_Q[MT * HDIM];
__device__ float g_K[MT * HDIM];
__device__ float g_V[MT * HDIM];
__device__ float g_A[(size_t)BATCH * TSEQ * TSEQ];   // relu^2 attention matrix
__device__ float g_W[MT * HDIM];            // U * (A @ V)

// ---------------- LayerNorm ----------------
__global__ void ln_kernel(const float* __restrict__ x,
                          const float* __restrict__ gamma,
                          const float* __restrict__ beta)
{
    int row = blockIdx.x;
    const float* xr = x + (size_t)row * HDIM;
    float* out = g_x + (size_t)row * HDIM;

    float s = 0.f, s2 = 0.f;
    for (int i = threadIdx.x; i < HDIM; i += 256) {
        float v = xr[i];
        s += v; s2 += v * v;
    }
    __shared__ float red0[32], red1[32];
    #pragma unroll
    for (int o = 16; o; o >>= 1) {
        s  += __shfl_down_sync(0xffffffffu, s,  o);
        s2 += __shfl_down_sync(0xffffffffu, s2, o);
    }
    int w = threadIdx.x >> 5, l = threadIdx.x & 31;
    if (l == 0) { red0[w] = s; red1[w] = s2; }
    __syncthreads();
    if (threadIdx.x < 32) {
        s  = (l < 8) ? red0[l] : 0.f;
        s2 = (l < 8) ? red1[l] : 0.f;
        #pragma unroll
        for (int o = 4; o; o >>= 1) {
            s  += __shfl_down_sync(0xffffffffu, s,  o);
            s2 += __shfl_down_sync(0xffffffffu, s2, o);
        }
        if (l == 0) { red0[0] = s; red1[0] = s2; }
    }
    __syncthreads();
    float mu  = red0[0] * (1.f / HDIM);
    float var = red1[0] * (1.f / HDIM) - mu * mu;
    float inv = rsqrtf(var + 1e-5f);
    for (int i = threadIdx.x; i < HDIM; i += 256) {
        out[i] = (xr[i] - mu) * inv * gamma[i] + beta[i];
    }
}

// ---------------- SGEMM tile cores ----------------
// 128x128 tile, 256 threads, 8x8 per-thread (4+4 split), kTile=16.
// NT: C[m,n] = sum_k A[m,k] * B[n,k]   (A: lda, B: ldb, both K-contiguous)
__device__ __forceinline__ void sgemm_nt_tile(
    const float* __restrict__ A, int lda,
    const float* __restrict__ Bm, int ldb,
    int K, float acc[8][8],
    float (*As)[132], float (*Bs)[132])
{
    int tid = threadIdx.x;
    for (int k0 = 0; k0 < K; k0 += 16) {
        #pragma unroll
        for (int it = 0; it < 2; ++it) {
            int idx = tid + it * 256;
            int r  = idx >> 2;
            int c4 = (idx & 3) * 4;
            float4 va = *(const float4*)(A + (size_t)r * lda + k0 + c4);
            As[c4 + 0][r] = va.x; As[c4 + 1][r] = va.y;
            As[c4 + 2][r] = va.z; As[c4 + 3][r] = va.w;
            float4 vb = *(const float4*)(Bm + (size_t)r * ldb + k0 + c4);
            Bs[c4 + 0][r] = vb.x; Bs[c4 + 1][r] = vb.y;
            Bs[c4 + 2][r] = vb.z; Bs[c4 + 3][r] = vb.w;
        }
        __syncthreads();
        int tx = tid & 15, ty = tid >> 4;
        #pragma unroll
        for (int kk = 0; kk < 16; ++kk) {
            float4 a0 = *(const float4*)&As[kk][ty * 4];
            float4 a1 = *(const float4*)&As[kk][ty * 4 + 64];
            float4 b0 = *(const float4*)&Bs[kk][tx * 4];
            float4 b1 = *(const float4*)&Bs[kk][tx * 4 + 64];
            float a[8] = {a0.x, a0.y, a0.z, a0.w, a1.x, a1.y, a1.z, a1.w};
            float b[8] = {b0.x, b0.y, b0.z, b0.w, b1.x, b1.y, b1.z, b1.w};
            #pragma unroll
            for (int i = 0; i < 8; ++i)
                #pragma unroll
                for (int j = 0; j < 8; ++j)
                    acc[i][j] = fmaf(a[i], b[j], acc[i][j]);
        }
        __syncthreads();
    }
}

// NN: C[m,n] = sum_k A[m,k] * B[k,n]   (B rows are N-contiguous; Bm pre-offset by n0)
__device__ __forceinline__ void sgemm_nn_tile(
    const float* __restrict__ A, int lda,
    const float* __restrict__ Bm, int ldb,
    int K, float acc[8][8],
    float (*As)[132], float (*Bs)[132])
{
    int tid = threadIdx.x;
    for (int k0 = 0; k0 < K; k0 += 16) {
        #pragma unroll
        for (int it = 0; it < 2; ++it) {
            int idx = tid + it * 256;
            int r  = idx >> 2;
            int c4 = (idx & 3) * 4;
            float4 va = *(const float4*)(A + (size_t)r * lda + k0 + c4);
            As[c4 + 0][r] = va.x; As[c4 + 1][r] = va.y;
            As[c4 + 2][r] = va.z; As[c4 + 3][r] = va.w;
            int rb = idx >> 5;            // 0..15
            int cb = (idx & 31) * 4;      // 0..124
            float4 vb = *(const float4*)(Bm + (size_t)(k0 + rb) * ldb + cb);
            *(float4*)&Bs[rb][cb] = vb;
        }
        __syncthreads();
        int tx = tid & 15, ty = tid >> 4;
        #pragma unroll
        for (int kk = 0; kk < 16; ++kk) {
            float4 a0 = *(const float4*)&As[kk][ty * 4];
            float4 a1 = *(const float4*)&As[kk][ty * 4 + 64];
            float4 b0 = *(const float4*)&Bs[kk][tx * 4];
            float4 b1 = *(const float4*)&Bs[kk][tx * 4 + 64];
            float a[8] = {a0.x, a0.y, a0.z, a0.w, a1.x, a1.y, a1.z, a1.w};
            float b[8] = {b0.x, b0.y, b0.z, b0.w, b1.x, b1.y, b1.z, b1.w};
            #pragma unroll
            for (int i = 0; i < 8; ++i)
                #pragma unroll
                for (int j = 0; j < 8; ++j)
                    acc[i][j] = fmaf(a[i], b[j], acc[i][j]);
        }
        __syncthreads();
    }
}

__device__ __forceinline__ float silu_f(float v) {
    return v / (1.f + expf(-v));
}

// ---------------- projections: {U,Q,K,V} = silu(x @ W^T + b) ----------------
__global__ void proj_kernel(const float* __restrict__ Wu, const float* __restrict__ bu,
                            const float* __restrict__ Wq, const float* __restrict__ bq,
                            const float* __restrict__ Wk, const float* __restrict__ bk,
                            const float* __restrict__ Wv, const float* __restrict__ bv)
{
    __shared__ float As[16][132], Bs[16][132];
    const float* W; const float* bias; float* C;
    switch (blockIdx.z) {
        case 0:  W = Wu; bias = bu; C = g_U; break;
        case 1:  W = Wq; bias = bq; C = g_Q; break;
        case 2:  W = Wk; bias = bk; C = g_K; break;
        default: W = Wv; bias = bv; C = g_V; break;
    }
    int m0 = blockIdx.y * 128, n0 = blockIdx.x * 128;
    float acc[8][8] = {};
    sgemm_nt_tile(g_x + (size_t)m0 * HDIM, HDIM, W + (size_t)n0 * HDIM, HDIM, HDIM, acc, As, Bs);

    int tx = threadIdx.x & 15, ty = threadIdx.x >> 4;
    #pragma unroll
    for (int i = 0; i < 8; ++i) {
        int r = m0 + ty * 4 + (i < 4 ? i : i + 60);
        #pragma unroll
        for (int jh = 0; jh < 2; ++jh) {
            int cbase = n0 + tx * 4 + jh * 64;
            float4 o;
            float* po = &o.x;
            #pragma unroll
            for (int j = 0; j < 4; ++j) {
                float v = acc[i][jh * 4 + j] + bias[cbase + j];
                po[j] = silu_f(v);
            }
            *(float4*)&C[(size_t)r * HDIM + cbase] = o;
        }
    }
}

// ---------------- sim: A = relu(Q K^T / sqrt(T))^2 ----------------
__global__ void sim_kernel()
{
    __shared__ float As[16][132], Bs[16][132];
    int b = blockIdx.z;
    int m0 = blockIdx.y * 128, n0 = blockIdx.x * 128;
    const float* Qb = g_Q + (size_t)b * TSEQ * HDIM;
    const float* Kb = g_K + (size_t)b * TSEQ * HDIM;
    float* C = g_A + (size_t)b * TSEQ * TSEQ;
    float acc[8][8] = {};
    sgemm_nt_tile(Qb + (size_t)m0 * HDIM, HDIM, Kb + (size_t)n0 * HDIM, HDIM, HDIM, acc, As, Bs);

    const float scale = 0.022097086912079608f;  // 1/sqrt(2048)
    int tx = threadIdx.x & 15, ty = threadIdx.x >> 4;
    #pragma unroll
    for (int i = 0; i < 8; ++i) {
        int r = m0 + ty * 4 + (i < 4 ? i : i + 60);
        #pragma unroll
        for (int jh = 0; jh < 2; ++jh) {
            int cbase = n0 + tx * 4 + jh * 64;
            float4 o;
            float* po = &o.x;
            #pragma unroll
            for (int j = 0; j < 4; ++j) {
                float v = fmaxf(acc[i][jh * 4 + j] * scale, 0.f);
                po[j] = v * v;
            }
            *(float4*)&C[(size_t)r * TSEQ + cbase] = o;
        }
    }
}

// ---------------- AV: W = U * (A @ V) ----------------
__global__ void av_kernel()
{
    __shared__ float As[16][132], Bs[16][132];
    int b = blockIdx.z;
    int m0 = blockIdx.y * 128, n0 = blockIdx.x * 128;
    const float* Ab = g_A + (size_t)b * TSEQ * TSEQ;
    const float* Vb = g_V + (size_t)b * TSEQ * HDIM;
    const float* Ub = g_U + (size_t)b * TSEQ * HDIM;
    float* C = g_W + (size_t)b * TSEQ * HDIM;
    float acc[8][8] = {};
    sgemm_nn_tile(Ab + (size_t)m0 * TSEQ, TSEQ, Vb + n0, HDIM, TSEQ, acc, As, Bs);

    int tx = threadIdx.x & 15, ty = threadIdx.x >> 4;
    #pragma unroll
    for (int i = 0; i < 8; ++i) {
        int r = m0 + ty * 4 + (i < 4 ? i : i + 60);
        #pragma unroll
        for (int jh = 0; jh < 2; ++jh) {
            int cbase = n0 + tx * 4 + jh * 64;
            float4 u = *(const float4*)&Ub[(size_t)r * HDIM + cbase];
            const float* pu = &u.x;
            float4 o;
            float* po = &o.x;
            #pragma unroll
            for (int j = 0; j < 4; ++j)
                po[j] = acc[i][jh * 4 + j] * pu[j];
            *(float4*)&C[(size_t)r * HDIM + cbase] = o;
        }
    }
}

// ---------------- final: out = W @ Wo^T + bo ----------------
__global__ void fin_kernel(const float* __restrict__ Wo, const float* __restrict__ bo,
                           float* __restrict__ out)
{
    __shared__ float As[16][132], Bs[16][132];
    int m0 = blockIdx.y * 128, n0 = blockIdx.x * 128;
    float acc[8][8] = {};
    sgemm_nt_tile(g_W + (size_t)m0 * HDIM, HDIM, Wo + (size_t)n0 * HDIM, HDIM, HDIM, acc, As, Bs);

    int tx = threadIdx.x & 15, ty = threadIdx.x >> 4;
    #pragma unroll
    for (int i = 0; i < 8; ++i) {
        int r = m0 + ty * 4 + (i < 4 ? i : i + 60);
        #pragma unroll
        for (int jh = 0; jh < 2; ++jh) {
            int cbase = n0 + tx * 4 + jh * 64;
            float4 o;
            float* po = &o.x;
            #pragma unroll
            for (int j = 0; j < 4; ++j)
                po[j] = acc[i][jh * 4 + j] + bo[cbase + j];
            *(float4*)&out[(size_t)r * HDIM + cbase] = o;
        }
    }
}

// ---------------- launch ----------------
extern "C" void kernel_launch(void* const* d_in, const int* in_sizes, int n_in,
                              void* d_out, int out_size)
{
    const float* hs    = (const float*)d_in[0];
    const float* gamma = (const float*)d_in[1];
    const float* beta  = (const float*)d_in[2];
    const float* Wu    = (const float*)d_in[3];
    const float* bu    = (const float*)d_in[4];
    const float* Wq    = (const float*)d_in[5];
    const float* bq    = (const float*)d_in[6];
    const float* Wk    = (const float*)d_in[7];
    const float* bk    = (const float*)d_in[8];
    const float* Wv    = (const float*)d_in[9];
    const float* bv    = (const float*)d_in[10];
    const float* Wo    = (const float*)d_in[11];
    const float* bo    = (const float*)d_in[12];
    float* out = (float*)d_out;

    ln_kernel<<<MT, 256>>>(hs, gamma, beta);

    dim3 gp(HDIM / 128, MT / 128, 4);            // (6, 64, 4)
    proj_kernel<<<gp, 256>>>(Wu, bu, Wq, bq, Wk, bk, Wv, bv);

    dim3 gs(TSEQ / 128, TSEQ / 128, BATCH);      // (16, 16, 4)
    sim_kernel<<<gs, 256>>>();

    dim3 ga(HDIM / 128, TSEQ / 128, BATCH);      // (6, 16, 4)
    av_kernel<<<ga, 256>>>();

    dim3 gf(HDIM / 128, MT / 128);               // (6, 64)
    fin_kernel<<<gf, 256>>>(Wo, bo, out);
}

// round 2
// speedup vs baseline: 2.9512x; 2.9512x over previous
#include <cuda_runtime.h>
#include <cstdint>
#include <cmath>

#define HDIM 768
#define TSEQ 2048
#define BATCH 4
#define MT (BATCH * TSEQ)   // 8192

// ---------------- scratch ----------------
__device__ float g_x [MT * HDIM];
__device__ float g_U [MT * HDIM];
__device__ float g_Q [MT * HDIM];
__device__ float g_K [MT * HDIM];
__device__ float g_V [MT * HDIM];
__device__ float g_Vt[MT * HDIM];                    // V transposed per batch: [d][t]
__device__ float g_A [(size_t)BATCH * TSEQ * TSEQ];
__device__ float g_W [MT * HDIM];

// ---------------- PTX helpers ----------------
__device__ __forceinline__ uint32_t smem_u32(const void* p) {
    return (uint32_t)__cvta_generic_to_shared(p);
}
__device__ __forceinline__ void cp16(uint32_t dst, const float* src) {
    asm volatile("cp.async.cg.shared.global [%0], [%1], 16;\n" :: "r"(dst), "l"(src));
}
__device__ __forceinline__ void cp_commit() { asm volatile("cp.async.commit_group;\n"); }
__device__ __forceinline__ void cp_wait1()  { asm volatile("cp.async.wait_group 1;\n" ::: "memory"); }
__device__ __forceinline__ uint32_t f2tf32(uint32_t x) {
    uint32_t y;
    asm("cvt.rna.tf32.f32 %0, %1;\n" : "=r"(y) : "r"(x));
    return y;
}
__device__ __forceinline__ void ldsm4(uint32_t addr, uint32_t& r0, uint32_t& r1,
                                      uint32_t& r2, uint32_t& r3) {
    asm volatile("ldmatrix.sync.aligned.m8n8.x4.shared.b16 {%0,%1,%2,%3}, [%4];\n"
                 : "=r"(r0), "=r"(r1), "=r"(r2), "=r"(r3) : "r"(addr));
}
__device__ __forceinline__ void mma_tf32(float c[4],
                                         uint32_t a0, uint32_t a1, uint32_t a2, uint32_t a3,
                                         uint32_t b0, uint32_t b1) {
    asm volatile("mma.sync.aligned.m16n8k8.row.col.f32.tf32.tf32.f32 "
                 "{%0,%1,%2,%3}, {%4,%5,%6,%7}, {%8,%9}, {%0,%1,%2,%3};\n"
                 : "+f"(c[0]), "+f"(c[1]), "+f"(c[2]), "+f"(c[3])
                 : "r"(a0), "r"(a1), "r"(a2), "r"(a3), "r"(b0), "r"(b1));
}

// ---------------- GEMM core ----------------
// Block: 256 thr = 8 warps. Block tile 128(M) x 128(N), KT=16, 3-stage cp.async.
// Warp tile 64x32: wm = wid&1 (2 x 64 rows), wn = wid>>1 (4 x 32 cols).
// smem per stage: A 128x20 + B 128x20 floats (stride 20: conflict-free ldmatrix).
#define STAGE_FLOATS 5120
#define SMEM_BYTES   (3 * STAGE_FLOATS * 4)

__device__ __forceinline__ void copy_stage(float* base, const float* Ag, int lda,
                                           const float* Bg, int ldb, int k0, int tid) {
    float* sA = base;
    float* sB = base + 2560;
    int row = tid >> 2;
    int cb  = (tid & 3) * 4;
    cp16(smem_u32(sA + row * 20 + cb),        Ag + (size_t)row        * lda + k0 + cb);
    cp16(smem_u32(sA + (row + 64) * 20 + cb), Ag + (size_t)(row + 64) * lda + k0 + cb);
    cp16(smem_u32(sB + row * 20 + cb),        Bg + (size_t)row        * ldb + k0 + cb);
    cp16(smem_u32(sB + (row + 64) * 20 + cb), Bg + (size_t)(row + 64) * ldb + k0 + cb);
}

__device__ __forceinline__ void gemm_core(const float* Ag, int lda,
                                          const float* Bg, int ldb,
                                          int K, float acc[4][4][4]) {
    extern __shared__ float smem[];
    int tid = threadIdx.x;
    int l   = tid & 31;
    int wid = tid >> 5;
    int wm  = wid & 1;
    int wn  = wid >> 1;

    // per-lane ldmatrix byte offsets (A: 16 rows x 8k per x4; B: two 8x8 n-atoms per x4)
    uint32_t aOff = ((uint32_t)(wm * 64 + (l & 15)) * 20 + (l >> 4) * 4) * 4;
    uint32_t bOff = ((uint32_t)(wn * 32 + (l & 7) + ((l & 16) >> 1)) * 20 + ((l >> 3) & 1) * 4) * 4;

    int nk = K >> 4;
    copy_stage(smem,                Ag, lda, Bg, ldb, 0,  tid); cp_commit();
    copy_stage(smem + STAGE_FLOATS, Ag, lda, Bg, ldb, 16, tid); cp_commit();

    int s = 0;  // current stage
    for (int t = 0; t < nk; ++t) {
        cp_wait1();
        __syncthreads();
        int tn = t + 2;
        if (tn < nk) {
            int sn = tn - ((tn / 3) * 3);
            copy_stage(smem + sn * STAGE_FLOATS, Ag, lda, Bg, ldb, tn * 16, tid);
        }
        cp_commit();

        uint32_t sAu = smem_u32(smem + s * STAGE_FLOATS);
        uint32_t sBu = sAu + 2560 * 4;
        #pragma unroll
        for (int kk = 0; kk < 2; ++kk) {
            uint32_t aF[4][4], bF[4][2];
            #pragma unroll
            for (int p = 0; p < 2; ++p) {
                uint32_t x0, x1, x2, x3;
                ldsm4(sBu + bOff + p * 1280 + kk * 32, x0, x1, x2, x3);
                bF[2 * p][0]     = f2tf32(x0); bF[2 * p][1]     = f2tf32(x1);
                bF[2 * p + 1][0] = f2tf32(x2); bF[2 * p + 1][1] = f2tf32(x3);
            }
            #pragma unroll
            for (int i = 0; i < 4; ++i) {
                uint32_t x0, x1, x2, x3;
                ldsm4(sAu + aOff + i * 1280 + kk * 32, x0, x1, x2, x3);
                aF[i][0] = f2tf32(x0); aF[i][1] = f2tf32(x1);
                aF[i][2] = f2tf32(x2); aF[i][3] = f2tf32(x3);
            }
            #pragma unroll
            for (int i = 0; i < 4; ++i)
                #pragma unroll
                for (int j = 0; j < 4; ++j)
                    mma_tf32(acc[i][j], aF[i][0], aF[i][1], aF[i][2], aF[i][3],
                             bF[j][0], bF[j][1]);
        }
        ++s; if (s == 3) s = 0;
    }
}

// accumulator element (i,j,e): row = m0 + wm*64 + i*16 + (l>>2) + (e>=2?8:0)
//                              col = n0 + wn*32 + j*8  + (l&3)*2 + (e&1)

__device__ __forceinline__ float silu_f(float v) { return v / (1.f + expf(-v)); }

// ---------------- kernels ----------------
__global__ void ln_kernel(const float* __restrict__ x,
                          const float* __restrict__ gamma,
                          const float* __restrict__ beta) {
    int row = blockIdx.x;
    const float* xr = x + (size_t)row * HDIM;
    float* out = g_x + (size_t)row * HDIM;

    float s = 0.f, s2 = 0.f;
    for (int i = threadIdx.x; i < HDIM; i += 256) {
        float v = xr[i];
        s += v; s2 += v * v;
    }
    __shared__ float red0[32], red1[32];
    #pragma unroll
    for (int o = 16; o; o >>= 1) {
        s  += __shfl_down_sync(0xffffffffu, s,  o);
        s2 += __shfl_down_sync(0xffffffffu, s2, o);
    }
    int w = threadIdx.x >> 5, l = threadIdx.x & 31;
    if (l == 0) { red0[w] = s; red1[w] = s2; }
    __syncthreads();
    if (threadIdx.x < 32) {
        s  = (l < 8) ? red0[l] : 0.f;
        s2 = (l < 8) ? red1[l] : 0.f;
        #pragma unroll
        for (int o = 4; o; o >>= 1) {
            s  += __shfl_down_sync(0xffffffffu, s,  o);
            s2 += __shfl_down_sync(0xffffffffu, s2, o);
        }
        if (l == 0) { red0[0] = s; red1[0] = s2; }
    }
    __syncthreads();
    float mu  = red0[0] * (1.f / HDIM);
    float var = red1[0] * (1.f / HDIM) - mu * mu;
    float inv = rsqrtf(var + 1e-5f);
    for (int i = threadIdx.x; i < HDIM; i += 256) {
        out[i] = (xr[i] - mu) * inv * gamma[i] + beta[i];
    }
}

__global__ void __launch_bounds__(256) transpose_v_kernel() {
    __shared__ float tile[32][33];
    int b  = blockIdx.z;
    int t0 = blockIdx.x * 32;
    int d0 = blockIdx.y * 32;
    int tx = threadIdx.x & 31, ty = threadIdx.x >> 5;  // 32 x 8
    const float* Vb = g_V  + (size_t)b * TSEQ * HDIM;
    float*       Tb = g_Vt + (size_t)b * HDIM * TSEQ;
    #pragma unroll
    for (int q = 0; q < 4; ++q)
        tile[ty + q * 8][tx] = Vb[(size_t)(t0 + ty + q * 8) * HDIM + d0 + tx];
    __syncthreads();
    #pragma unroll
    for (int q = 0; q < 4; ++q)
        Tb[(size_t)(d0 + ty + q * 8) * TSEQ + t0 + tx] = tile[tx][ty + q * 8];
}

__global__ void __launch_bounds__(256, 2) proj_kernel(
        const float* __restrict__ Wu, const float* __restrict__ bu,
        const float* __restrict__ Wq, const float* __restrict__ bq,
        const float* __restrict__ Wk, const float* __restrict__ bk,
        const float* __restrict__ Wv, const float* __restrict__ bv) {
    const float* W; const float* bias; float* C;
    switch (blockIdx.z) {
        case 0:  W = Wu; bias = bu; C = g_U; break;
        case 1:  W = Wq; bias = bq; C = g_Q; break;
        case 2:  W = Wk; bias = bk; C = g_K; break;
        default: W = Wv; bias = bv; C = g_V; break;
    }
    int m0 = blockIdx.y * 128, n0 = blockIdx.x * 128;
    float acc[4][4][4] = {};
    gemm_core(g_x + (size_t)m0 * HDIM, HDIM, W + (size_t)n0 * HDIM, HDIM, HDIM, acc);

    int tid = threadIdx.x, l = tid & 31, wid = tid >> 5;
    int wm = wid & 1, wn = wid >> 1, g = l >> 2, tg = l & 3;
    #pragma unroll
    for (int i = 0; i < 4; ++i) {
        int r = m0 + wm * 64 + i * 16 + g;
        #pragma unroll
        for (int j = 0; j < 4; ++j) {
            int c = n0 + wn * 32 + j * 8 + tg * 2;
            float2 bb = *(const float2*)&bias[c];
            float2 o0 = { silu_f(acc[i][j][0] + bb.x), silu_f(acc[i][j][1] + bb.y) };
            float2 o1 = { silu_f(acc[i][j][2] + bb.x), silu_f(acc[i][j][3] + bb.y) };
            *(float2*)&C[(size_t)r * HDIM + c]       = o0;
            *(float2*)&C[(size_t)(r + 8) * HDIM + c] = o1;
        }
    }
}

__global__ void __launch_bounds__(256, 2) sim_kernel() {
    int b = blockIdx.z;
    int m0 = blockIdx.y * 128, n0 = blockIdx.x * 128;
    const float* Qb = g_Q + (size_t)b * TSEQ * HDIM;
    const float* Kb = g_K + (size_t)b * TSEQ * HDIM;
    float* C = g_A + (size_t)b * TSEQ * TSEQ;
    float acc[4][4][4] = {};
    gemm_core(Qb + (size_t)m0 * HDIM, HDIM, Kb + (size_t)n0 * HDIM, HDIM, HDIM, acc);

    const float scale = 0.022097086912079608f;  // 1/sqrt(2048)
    int tid = threadIdx.x, l = tid & 31, wid = tid >> 5;
    int wm = wid & 1, wn = wid >> 1, g = l >> 2, tg = l & 3;
    #pragma unroll
    for (int i = 0; i < 4; ++i) {
        int r = m0 + wm * 64 + i * 16 + g;
        #pragma unroll
        for (int j = 0; j < 4; ++j) {
            int c = n0 + wn * 32 + j * 8 + tg * 2;
            float v0 = fmaxf(acc[i][j][0] * scale, 0.f);
            float v1 = fmaxf(acc[i][j][1] * scale, 0.f);
            float v2 = fmaxf(acc[i][j][2] * scale, 0.f);
            float v3 = fmaxf(acc[i][j][3] * scale, 0.f);
            *(float2*)&C[(size_t)r * TSEQ + c]       = make_float2(v0 * v0, v1 * v1);
            *(float2*)&C[(size_t)(r + 8) * TSEQ + c] = make_float2(v2 * v2, v3 * v3);
        }
    }
}

__global__ void __launch_bounds__(256, 2) av_kernel() {
    int b = blockIdx.z;
    int m0 = blockIdx.y * 128, n0 = blockIdx.x * 128;
    const float* Ab = g_A  + (size_t)b * TSEQ * TSEQ;
    const float* Vt = g_Vt + (size_t)b * HDIM * TSEQ;
    const float* Ub = g_U  + (size_t)b * TSEQ * HDIM;
    float* C = g_W + (size_t)b * TSEQ * HDIM;
    float acc[4][4][4] = {};
    gemm_core(Ab + (size_t)m0 * TSEQ, TSEQ, Vt + (size_t)n0 * TSEQ, TSEQ, TSEQ, acc);

    int tid = threadIdx.x, l = tid & 31, wid = tid >> 5;
    int wm = wid & 1, wn = wid >> 1, g = l >> 2, tg = l & 3;
    #pragma unroll
    for (int i = 0; i < 4; ++i) {
        int r = m0 + wm * 64 + i * 16 + g;
        #pragma unroll
        for (int j = 0; j < 4; ++j) {
            int c = n0 + wn * 32 + j * 8 + tg * 2;
            float2 u0 = *(const float2*)&Ub[(size_t)r * HDIM + c];
            float2 u1 = *(const float2*)&Ub[(size_t)(r + 8) * HDIM + c];
            *(float2*)&C[(size_t)r * HDIM + c] =
                make_float2(acc[i][j][0] * u0.x, acc[i][j][1] * u0.y);
            *(float2*)&C[(size_t)(r + 8) * HDIM + c] =
                make_float2(acc[i][j][2] * u1.x, acc[i][j][3] * u1.y);
        }
    }
}

__global__ void __launch_bounds__(256, 2) fin_kernel(const float* __restrict__ Wo,
                                                     const float* __restrict__ bo,
                                                     float* __restrict__ out) {
    int m0 = blockIdx.y * 128, n0 = blockIdx.x * 128;
    float acc[4][4][4] = {};
    gemm_core(g_W + (size_t)m0 * HDIM, HDIM, Wo + (size_t)n0 * HDIM, HDIM, HDIM, acc);

    int tid = threadIdx.x, l = tid & 31, wid = tid >> 5;
    int wm = wid & 1, wn = wid >> 1, g = l >> 2, tg = l & 3;
    #pragma unroll
    for (int i = 0; i < 4; ++i) {
        int r = m0 + wm * 64 + i * 16 + g;
        #pragma unroll
        for (int j = 0; j < 4; ++j) {
            int c = n0 + wn * 32 + j * 8 + tg * 2;
            float2 bb = *(const float2*)&bo[c];
            *(float2*)&out[(size_t)r * HDIM + c] =
                make_float2(acc[i][j][0] + bb.x, acc[i][j][1] + bb.y);
            *(float2*)&out[(size_t)(r + 8) * HDIM + c] =
                make_float2(acc[i][j][2] + bb.x, acc[i][j][3] + bb.y);
        }
    }
}

// ---------------- launch ----------------
extern "C" void kernel_launch(void* const* d_in, const int* in_sizes, int n_in,
                              void* d_out, int out_size) {
    const float* hs    = (const float*)d_in[0];
    const float* gamma = (const float*)d_in[1];
    const float* beta  = (const float*)d_in[2];
    const float* Wu    = (const float*)d_in[3];
    const float* bu    = (const float*)d_in[4];
    const float* Wq    = (const float*)d_in[5];
    const float* bq    = (const float*)d_in[6];
    const float* Wk    = (const float*)d_in[7];
    const float* bk    = (const float*)d_in[8];
    const float* Wv    = (const float*)d_in[9];
    const float* bv    = (const float*)d_in[10];
    const float* Wo    = (const float*)d_in[11];
    const float* bo    = (const float*)d_in[12];
    float* out = (float*)d_out;

    cudaFuncSetAttribute(proj_kernel, cudaFuncAttributeMaxDynamicSharedMemorySize, SMEM_BYTES);
    cudaFuncSetAttribute(sim_kernel,  cudaFuncAttributeMaxDynamicSharedMemorySize, SMEM_BYTES);
    cudaFuncSetAttribute(av_kernel,   cudaFuncAttributeMaxDynamicSharedMemorySize, SMEM_BYTES);
    cudaFuncSetAttribute(fin_kernel,  cudaFuncAttributeMaxDynamicSharedMemorySize, SMEM_BYTES);

    ln_kernel<<<MT, 256>>>(hs, gamma, beta);

    dim3 gp(HDIM / 128, MT / 128, 4);                 // (6, 64, 4)
    proj_kernel<<<gp, 256, SMEM_BYTES>>>(Wu, bu, Wq, bq, Wk, bk, Wv, bv);

    dim3 gt(TSEQ / 32, HDIM / 32, BATCH);             // (64, 24, 4)
    transpose_v_kernel<<<gt, 256>>>();

    dim3 gs(TSEQ / 128, TSEQ / 128, BATCH);           // (16, 16, 4)
    sim_kernel<<<gs, 256, SMEM_BYTES>>>();

    dim3 ga(HDIM / 128, TSEQ / 128, BATCH);           // (6, 16, 4)
    av_kernel<<<ga, 256, SMEM_BYTES>>>();

    dim3 gf(HDIM / 128, MT / 128, 1);                 // (6, 64)
    fin_kernel<<<gf, 256, SMEM_BYTES>>>(Wo, bo, out);
}

// round 3
// speedup vs baseline: 2.9580x; 1.0023x over previous
#include <cuda_runtime.h>
#include <cstdint>
#include <cmath>

#define HDIM 768
#define TSEQ 2048
#define BATCH 4
#define MT (BATCH * TSEQ)   // 8192

// ---------------- scratch ----------------
__device__ float g_x [MT * HDIM];
__device__ float g_U [MT * HDIM];
__device__ float g_Q [MT * HDIM];
__device__ float g_K [MT * HDIM];
__device__ float g_V [MT * HDIM];
__device__ float g_Vt[MT * HDIM];                    // V transposed per batch: [d][t]
__device__ float g_A [(size_t)BATCH * TSEQ * TSEQ];
__device__ float g_W [MT * HDIM];

// ---------------- PTX helpers ----------------
__device__ __forceinline__ uint32_t smem_u32(const void* p) {
    return (uint32_t)__cvta_generic_to_shared(p);
}
__device__ __forceinline__ void cp16(uint32_t dst, const float* src) {
    asm volatile("cp.async.cg.shared.global [%0], [%1], 16;\n" :: "r"(dst), "l"(src));
}
__device__ __forceinline__ void cp_commit() { asm volatile("cp.async.commit_group;\n"); }
__device__ __forceinline__ void cp_wait1()  { asm volatile("cp.async.wait_group 1;\n" ::: "memory"); }
__device__ __forceinline__ uint32_t f2tf32(uint32_t x) {
    uint32_t y;
    asm("cvt.rna.tf32.f32 %0, %1;\n" : "=r"(y) : "r"(x));
    return y;
}
__device__ __forceinline__ void ldsm4(uint32_t addr, uint32_t& r0, uint32_t& r1,
                                      uint32_t& r2, uint32_t& r3) {
    asm volatile("ldmatrix.sync.aligned.m8n8.x4.shared.b16 {%0,%1,%2,%3}, [%4];\n"
                 : "=r"(r0), "=r"(r1), "=r"(r2), "=r"(r3) : "r"(addr));
}
__device__ __forceinline__ void mma_tf32(float c[4],
                                         uint32_t a0, uint32_t a1, uint32_t a2, uint32_t a3,
                                         uint32_t b0, uint32_t b1) {
    asm volatile("mma.sync.aligned.m16n8k8.row.col.f32.tf32.tf32.f32 "
                 "{%0,%1,%2,%3}, {%4,%5,%6,%7}, {%8,%9}, {%0,%1,%2,%3};\n"
                 : "+f"(c[0]), "+f"(c[1]), "+f"(c[2]), "+f"(c[3])
                 : "r"(a0), "r"(a1), "r"(a2), "r"(a3), "r"(b0), "r"(b1));
}

// ---------------- GEMM core ----------------
// Block: 256 thr = 8 warps. Block tile 128(M) x 128(N), KT=16, 3-stage cp.async.
// Warp tile 64x32: wm = wid&1 (2 x 64 rows), wn = wid>>1 (4 x 32 cols).
// smem per stage: A 128x20 + B 128x20 floats (stride 20: conflict-free ldmatrix).
#define STAGE_FLOATS 5120
#define SMEM_BYTES   (3 * STAGE_FLOATS * 4)

__device__ __forceinline__ void copy_stage(float* base, const float* Ag, int lda,
                                           const float* Bg, int ldb, int k0, int tid) {
    float* sA = base;
    float* sB = base + 2560;
    int row = tid >> 2;
    int cb  = (tid & 3) * 4;
    cp16(smem_u32(sA + row * 20 + cb),        Ag + (size_t)row        * lda + k0 + cb);
    cp16(smem_u32(sA + (row + 64) * 20 + cb), Ag + (size_t)(row + 64) * lda + k0 + cb);
    cp16(smem_u32(sB + row * 20 + cb),        Bg + (size_t)row        * ldb + k0 + cb);
    cp16(smem_u32(sB + (row + 64) * 20 + cb), Bg + (size_t)(row + 64) * ldb + k0 + cb);
}

__device__ __forceinline__ void gemm_core(const float* Ag, int lda,
                                          const float* Bg, int ldb,
                                          int K, float acc[4][4][4]) {
    extern __shared__ float smem[];
    int tid = threadIdx.x;
    int l   = tid & 31;
    int wid = tid >> 5;
    int wm  = wid & 1;
    int wn  = wid >> 1;

    // per-lane ldmatrix byte offsets (A: 16 rows x 8k per x4; B: two 8x8 n-atoms per x4)
    uint32_t aOff = ((uint32_t)(wm * 64 + (l & 15)) * 20 + (l >> 4) * 4) * 4;
    uint32_t bOff = ((uint32_t)(wn * 32 + (l & 7) + ((l & 16) >> 1)) * 20 + ((l >> 3) & 1) * 4) * 4;

    int nk = K >> 4;
    copy_stage(smem,                Ag, lda, Bg, ldb, 0,  tid); cp_commit();
    copy_stage(smem + STAGE_FLOATS, Ag, lda, Bg, ldb, 16, tid); cp_commit();

    int s = 0;  // current stage
    for (int t = 0; t < nk; ++t) {
        cp_wait1();
        __syncthreads();
        int tn = t + 2;
        if (tn < nk) {
            int sn = tn - ((tn / 3) * 3);
            copy_stage(smem + sn * STAGE_FLOATS, Ag, lda, Bg, ldb, tn * 16, tid);
        }
        cp_commit();

        uint32_t sAu = smem_u32(smem + s * STAGE_FLOATS);
        uint32_t sBu = sAu + 2560 * 4;
        #pragma unroll
        for (int kk = 0; kk < 2; ++kk) {
            uint32_t aF[4][4], bF[4][2];
            #pragma unroll
            for (int p = 0; p < 2; ++p) {
                uint32_t x0, x1, x2, x3;
                ldsm4(sBu + bOff + p * 1280 + kk * 32, x0, x1, x2, x3);
                bF[2 * p][0]     = f2tf32(x0); bF[2 * p][1]     = f2tf32(x1);
                bF[2 * p + 1][0] = f2tf32(x2); bF[2 * p + 1][1] = f2tf32(x3);
            }
            #pragma unroll
            for (int i = 0; i < 4; ++i) {
                uint32_t x0, x1, x2, x3;
                ldsm4(sAu + aOff + i * 1280 + kk * 32, x0, x1, x2, x3);
                aF[i][0] = f2tf32(x0); aF[i][1] = f2tf32(x1);
                aF[i][2] = f2tf32(x2); aF[i][3] = f2tf32(x3);
            }
            #pragma unroll
            for (int i = 0; i < 4; ++i)
                #pragma unroll
                for (int j = 0; j < 4; ++j)
                    mma_tf32(acc[i][j], aF[i][0], aF[i][1], aF[i][2], aF[i][3],
                             bF[j][0], bF[j][1]);
        }
        ++s; if (s == 3) s = 0;
    }
}

// accumulator element (i,j,e): row = m0 + wm*64 + i*16 + (l>>2) + (e>=2?8:0)
//                              col = n0 + wn*32 + j*8  + (l&3)*2 + (e&1)

__device__ __forceinline__ float silu_f(float v) { return v / (1.f + expf(-v)); }

// ---------------- kernels ----------------
__global__ void ln_kernel(const float* __restrict__ x,
                          const float* __restrict__ gamma,
                          const float* __restrict__ beta) {
    int row = blockIdx.x;
    const float* xr = x + (size_t)row * HDIM;
    float* out = g_x + (size_t)row * HDIM;

    float s = 0.f, s2 = 0.f;
    for (int i = threadIdx.x; i < HDIM; i += 256) {
        float v = xr[i];
        s += v; s2 += v * v;
    }
    __shared__ float red0[32], red1[32];
    #pragma unroll
    for (int o = 16; o; o >>= 1) {
        s  += __shfl_down_sync(0xffffffffu, s,  o);
        s2 += __shfl_down_sync(0xffffffffu, s2, o);
    }
    int w = threadIdx.x >> 5, l = threadIdx.x & 31;
    if (l == 0) { red0[w] = s; red1[w] = s2; }
    __syncthreads();
    if (threadIdx.x < 32) {
        s  = (l < 8) ? red0[l] : 0.f;
        s2 = (l < 8) ? red1[l] : 0.f;
        #pragma unroll
        for (int o = 4; o; o >>= 1) {
            s  += __shfl_down_sync(0xffffffffu, s,  o);
            s2 += __shfl_down_sync(0xffffffffu, s2, o);
        }
        if (l == 0) { red0[0] = s; red1[0] = s2; }
    }
    __syncthreads();
    float mu  = red0[0] * (1.f / HDIM);
    float var = red1[0] * (1.f / HDIM) - mu * mu;
    float inv = rsqrtf(var + 1e-5f);
    for (int i = threadIdx.x; i < HDIM; i += 256) {
        out[i] = (xr[i] - mu) * inv * gamma[i] + beta[i];
    }
}

__global__ void __launch_bounds__(256) transpose_v_kernel() {
    __shared__ float tile[32][33];
    int b  = blockIdx.z;
    int t0 = blockIdx.x * 32;
    int d0 = blockIdx.y * 32;
    int tx = threadIdx.x & 31, ty = threadIdx.x >> 5;  // 32 x 8
    const float* Vb = g_V  + (size_t)b * TSEQ * HDIM;
    float*       Tb = g_Vt + (size_t)b * HDIM * TSEQ;
    #pragma unroll
    for (int q = 0; q < 4; ++q)
        tile[ty + q * 8][tx] = Vb[(size_t)(t0 + ty + q * 8) * HDIM + d0 + tx];
    __syncthreads();
    #pragma unroll
    for (int q = 0; q < 4; ++q)
        Tb[(size_t)(d0 + ty + q * 8) * TSEQ + t0 + tx] = tile[tx][ty + q * 8];
}

__global__ void __launch_bounds__(256, 2) proj_kernel(
        const float* __restrict__ Wu, const float* __restrict__ bu,
        const float* __restrict__ Wq, const float* __restrict__ bq,
        const float* __restrict__ Wk, const float* __restrict__ bk,
        const float* __restrict__ Wv, const float* __restrict__ bv) {
    const float* W; const float* bias; float* C;
    switch (blockIdx.z) {
        case 0:  W = Wu; bias = bu; C = g_U; break;
        case 1:  W = Wq; bias = bq; C = g_Q; break;
        case 2:  W = Wk; bias = bk; C = g_K; break;
        default: W = Wv; bias = bv; C = g_V; break;
    }
    int m0 = blockIdx.y * 128, n0 = blockIdx.x * 128;
    float acc[4][4][4] = {};
    gemm_core(g_x + (size_t)m0 * HDIM, HDIM, W + (size_t)n0 * HDIM, HDIM, HDIM, acc);

    int tid = threadIdx.x, l = tid & 31, wid = tid >> 5;
    int wm = wid & 1, wn = wid >> 1, g = l >> 2, tg = l & 3;
    #pragma unroll
    for (int i = 0; i < 4; ++i) {
        int r = m0 + wm * 64 + i * 16 + g;
        #pragma unroll
        for (int j = 0; j < 4; ++j) {
            int c = n0 + wn * 32 + j * 8 + tg * 2;
            float2 bb = *(const float2*)&bias[c];
            float2 o0 = { silu_f(acc[i][j][0] + bb.x), silu_f(acc[i][j][1] + bb.y) };
            float2 o1 = { silu_f(acc[i][j][2] + bb.x), silu_f(acc[i][j][3] + bb.y) };
            *(float2*)&C[(size_t)r * HDIM + c]       = o0;
            *(float2*)&C[(size_t)(r + 8) * HDIM + c] = o1;
        }
    }
}

__global__ void __launch_bounds__(256, 2) sim_kernel() {
    int b = blockIdx.z;
    int m0 = blockIdx.y * 128, n0 = blockIdx.x * 128;
    const float* Qb = g_Q + (size_t)b * TSEQ * HDIM;
    const float* Kb = g_K + (size_t)b * TSEQ * HDIM;
    float* C = g_A + (size_t)b * TSEQ * TSEQ;
    float acc[4][4][4] = {};
    gemm_core(Qb + (size_t)m0 * HDIM, HDIM, Kb + (size_t)n0 * HDIM, HDIM, HDIM, acc);

    const float scale = 0.022097086912079608f;  // 1/sqrt(2048)
    int tid = threadIdx.x, l = tid & 31, wid = tid >> 5;
    int wm = wid & 1, wn = wid >> 1, g = l >> 2, tg = l & 3;
    #pragma unroll
    for (int i = 0; i < 4; ++i) {
        int r = m0 + wm * 64 + i * 16 + g;
        #pragma unroll
        for (int j = 0; j < 4; ++j) {
            int c = n0 + wn * 32 + j * 8 + tg * 2;
            float v0 = fmaxf(acc[i][j][0] * scale, 0.f);
            float v1 = fmaxf(acc[i][j][1] * scale, 0.f);
            float v2 = fmaxf(acc[i][j][2] * scale, 0.f);
            float v3 = fmaxf(acc[i][j][3] * scale, 0.f);
            *(float2*)&C[(size_t)r * TSEQ + c]       = make_float2(v0 * v0, v1 * v1);
            *(float2*)&C[(size_t)(r + 8) * TSEQ + c] = make_float2(v2 * v2, v3 * v3);
        }
    }
}

__global__ void __launch_bounds__(256, 2) av_kernel() {
    int b = blockIdx.z;
    int m0 = blockIdx.y * 128, n0 = blockIdx.x * 128;
    const float* Ab = g_A  + (size_t)b * TSEQ * TSEQ;
    const float* Vt = g_Vt + (size_t)b * HDIM * TSEQ;
    const float* Ub = g_U  + (size_t)b * TSEQ * HDIM;
    float* C = g_W + (size_t)b * TSEQ * HDIM;
    float acc[4][4][4] = {};
    gemm_core(Ab + (size_t)m0 * TSEQ, TSEQ, Vt + (size_t)n0 * TSEQ, TSEQ, TSEQ, acc);

    int tid = threadIdx.x, l = tid & 31, wid = tid >> 5;
    int wm = wid & 1, wn = wid >> 1, g = l >> 2, tg = l & 3;
    #pragma unroll
    for (int i = 0; i < 4; ++i) {
        int r = m0 + wm * 64 + i * 16 + g;
        #pragma unroll
        for (int j = 0; j < 4; ++j) {
            int c = n0 + wn * 32 + j * 8 + tg * 2;
            float2 u0 = *(const float2*)&Ub[(size_t)r * HDIM + c];
            float2 u1 = *(const float2*)&Ub[(size_t)(r + 8) * HDIM + c];
            *(float2*)&C[(size_t)r * HDIM + c] =
                make_float2(acc[i][j][0] * u0.x, acc[i][j][1] * u0.y);
            *(float2*)&C[(size_t)(r + 8) * HDIM + c] =
                make_float2(acc[i][j][2] * u1.x, acc[i][j][3] * u1.y);
        }
    }
}

__global__ void __launch_bounds__(256, 2) fin_kernel(const float* __restrict__ Wo,
                                                     const float* __restrict__ bo,
                                                     float* __restrict__ out) {
    int m0 = blockIdx.y * 128, n0 = blockIdx.x * 128;
    float acc[4][4][4] = {};
    gemm_core(g_W + (size_t)m0 * HDIM, HDIM, Wo + (size_t)n0 * HDIM, HDIM, HDIM, acc);

    int tid = threadIdx.x, l = tid & 31, wid = tid >> 5;
    int wm = wid & 1, wn = wid >> 1, g = l >> 2, tg = l & 3;
    #pragma unroll
    for (int i = 0; i < 4; ++i) {
        int r = m0 + wm * 64 + i * 16 + g;
        #pragma unroll
        for (int j = 0; j < 4; ++j) {
            int c = n0 + wn * 32 + j * 8 + tg * 2;
            float2 bb = *(const float2*)&bo[c];
            *(float2*)&out[(size_t)r * HDIM + c] =
                make_float2(acc[i][j][0] + bb.x, acc[i][j][1] + bb.y);
            *(float2*)&out[(size_t)(r + 8) * HDIM + c] =
                make_float2(acc[i][j][2] + bb.x, acc[i][j][3] + bb.y);
        }
    }
}

// ---------------- launch ----------------
extern "C" void kernel_launch(void* const* d_in, const int* in_sizes, int n_in,
                              void* d_out, int out_size) {
    const float* hs    = (const float*)d_in[0];
    const float* gamma = (const float*)d_in[1];
    const float* beta  = (const float*)d_in[2];
    const float* Wu    = (const float*)d_in[3];
    const float* bu    = (const float*)d_in[4];
    const float* Wq    = (const float*)d_in[5];
    const float* bq    = (const float*)d_in[6];
    const float* Wk    = (const float*)d_in[7];
    const float* bk    = (const float*)d_in[8];
    const float* Wv    = (const float*)d_in[9];
    const float* bv    = (const float*)d_in[10];
    const float* Wo    = (const float*)d_in[11];
    const float* bo    = (const float*)d_in[12];
    float* out = (float*)d_out;

    cudaFuncSetAttribute(proj_kernel, cudaFuncAttributeMaxDynamicSharedMemorySize, SMEM_BYTES);
    cudaFuncSetAttribute(sim_kernel,  cudaFuncAttributeMaxDynamicSharedMemorySize, SMEM_BYTES);
    cudaFuncSetAttribute(av_kernel,   cudaFuncAttributeMaxDynamicSharedMemorySize, SMEM_BYTES);
    cudaFuncSetAttribute(fin_kernel,  cudaFuncAttributeMaxDynamicSharedMemorySize, SMEM_BYTES);

    ln_kernel<<<MT, 256>>>(hs, gamma, beta);

    dim3 gp(HDIM / 128, MT / 128, 4);                 // (6, 64, 4)
    proj_kernel<<<gp, 256, SMEM_BYTES>>>(Wu, bu, Wq, bq, Wk, bk, Wv, bv);

    dim3 gt(TSEQ / 32, HDIM / 32, BATCH);             // (64, 24, 4)
    transpose_v_kernel<<<gt, 256>>>();

    dim3 gs(TSEQ / 128, TSEQ / 128, BATCH);           // (16, 16, 4)
    sim_kernel<<<gs, 256, SMEM_BYTES>>>();

    dim3 ga(HDIM / 128, TSEQ / 128, BATCH);           // (6, 16, 4)
    av_kernel<<<ga, 256, SMEM_BYTES>>>();

    dim3 gf(HDIM / 128, MT / 128, 1);                 // (6, 64)
    fin_kernel<<<gf, 256, SMEM_BYTES>>>(Wo, bo, out);
}

// round 4
// speedup vs baseline: 3.2585x; 1.1016x over previous
#include <cuda_runtime.h>
#include <cstdint>
#include <cmath>

#define HDIM 768
#define TSEQ 2048
#define BATCH 4
#define MT (BATCH * TSEQ)   // 8192

// ---------------- scratch ----------------
__device__ float g_x [MT * HDIM];
__device__ float g_U [MT * HDIM];
__device__ float g_Q [MT * HDIM];
__device__ float g_K [MT * HDIM];
__device__ float g_Vt[MT * HDIM];                    // V transposed per batch: [d][t]
__device__ float g_A [(size_t)BATCH * TSEQ * TSEQ];
__device__ float g_W [MT * HDIM];
// tf32-rounded weights
__device__ float g_Wu[HDIM * HDIM];
__device__ float g_Wq[HDIM * HDIM];
__device__ float g_Wk[HDIM * HDIM];
__device__ float g_Wv[HDIM * HDIM];
__device__ float g_Wo[HDIM * HDIM];

// ---------------- PTX helpers ----------------
__device__ __forceinline__ uint32_t smem_u32(const void* p) {
    return (uint32_t)__cvta_generic_to_shared(p);
}
__device__ __forceinline__ void cp16(uint32_t dst, const float* src) {
    asm volatile("cp.async.cg.shared.global [%0], [%1], 16;\n" :: "r"(dst), "l"(src));
}
__device__ __forceinline__ void cp_commit() { asm volatile("cp.async.commit_group;\n"); }
__device__ __forceinline__ float rtf(float v) {   // round-to-nearest tf32
    uint32_t y;
    asm("cvt.rna.tf32.f32 %0, %1;\n" : "=r"(y) : "f"(v));
    return __uint_as_float(y);
}
__device__ __forceinline__ void ldsm4(uint32_t addr, uint32_t& r0, uint32_t& r1,
                                      uint32_t& r2, uint32_t& r3) {
    asm volatile("ldmatrix.sync.aligned.m8n8.x4.shared.b16 {%0,%1,%2,%3}, [%4];\n"
                 : "=r"(r0), "=r"(r1), "=r"(r2), "=r"(r3) : "r"(addr));
}
__device__ __forceinline__ void mma_tf32(float c[4],
                                         uint32_t a0, uint32_t a1, uint32_t a2, uint32_t a3,
                                         uint32_t b0, uint32_t b1) {
    asm volatile("mma.sync.aligned.m16n8k8.row.col.f32.tf32.tf32.f32 "
                 "{%0,%1,%2,%3}, {%4,%5,%6,%7}, {%8,%9}, {%0,%1,%2,%3};\n"
                 : "+f"(c[0]), "+f"(c[1]), "+f"(c[2]), "+f"(c[3])
                 : "r"(a0), "r"(a1), "r"(a2), "r"(a3), "r"(b0), "r"(b1));
}

// ---------------- GEMM core ----------------
// Block: 256 thr = 8 warps. Block tile 128(M) x 128(N), KT=16, 4-stage cp.async.
// Warp tile 64x32: wm = wid&1, wn = wid>>1.
// smem per stage: A 128x20 + B 128x20 floats (stride 20: conflict-free ldmatrix).
// All operands are PRE-ROUNDED to tf32 in gmem -> no cvt in the inner loop
// (tf32 mma truncates low mantissa bits; identity on pre-rounded data).
#define STAGE_FLOATS 5120
#define NSTAGE 4
#define SMEM_BYTES   (NSTAGE * STAGE_FLOATS * 4)

__device__ __forceinline__ void copy_stage(float* base, const float* Ag, int lda,
                                           const float* Bg, int ldb, int k0, int tid) {
    float* sA = base;
    float* sB = base + 2560;
    int row = tid >> 2;
    int cb  = (tid & 3) * 4;
    cp16(smem_u32(sA + row * 20 + cb),        Ag + (size_t)row        * lda + k0 + cb);
    cp16(smem_u32(sA + (row + 64) * 20 + cb), Ag + (size_t)(row + 64) * lda + k0 + cb);
    cp16(smem_u32(sB + row * 20 + cb),        Bg + (size_t)row        * ldb + k0 + cb);
    cp16(smem_u32(sB + (row + 64) * 20 + cb), Bg + (size_t)(row + 64) * ldb + k0 + cb);
}

__device__ __forceinline__ void gemm_core(const float* Ag, int lda,
                                          const float* Bg, int ldb,
                                          int K, float acc[4][4][4]) {
    extern __shared__ float smem[];
    int tid = threadIdx.x;
    int l   = tid & 31;
    int wid = tid >> 5;
    int wm  = wid & 1;
    int wn  = wid >> 1;

    uint32_t aOff = ((uint32_t)(wm * 64 + (l & 15)) * 20 + (l >> 4) * 4) * 4;
    uint32_t bOff = ((uint32_t)(wn * 32 + (l & 7) + ((l & 16) >> 1)) * 20 + ((l >> 3) & 1) * 4) * 4;

    int nk = K >> 4;   // always >= 48 here
    copy_stage(smem,                    Ag, lda, Bg, ldb, 0,  tid); cp_commit();
    copy_stage(smem + STAGE_FLOATS,     Ag, lda, Bg, ldb, 16, tid); cp_commit();
    copy_stage(smem + 2 * STAGE_FLOATS, Ag, lda, Bg, ldb, 32, tid); cp_commit();

    for (int t = 0; t < nk; ++t) {
        asm volatile("cp.async.wait_group 2;\n" ::: "memory");
        __syncthreads();
        int tn = t + 3;
        if (tn < nk) {
            copy_stage(smem + (tn & 3) * STAGE_FLOATS, Ag, lda, Bg, ldb, tn * 16, tid);
        }
        cp_commit();

        uint32_t sAu = smem_u32(smem + (t & 3) * STAGE_FLOATS);
        uint32_t sBu = sAu + 2560 * 4;
        #pragma unroll
        for (int kk = 0; kk < 2; ++kk) {
            uint32_t aF[4][4], bF[4][2];
            ldsm4(sBu + bOff +        kk * 32, bF[0][0], bF[0][1], bF[1][0], bF[1][1]);
            ldsm4(sBu + bOff + 1280 + kk * 32, bF[2][0], bF[2][1], bF[3][0], bF[3][1]);
            #pragma unroll
            for (int i = 0; i < 4; ++i)
                ldsm4(sAu + aOff + i * 1280 + kk * 32,
                      aF[i][0], aF[i][1], aF[i][2], aF[i][3]);
            #pragma unroll
            for (int i = 0; i < 4; ++i)
                #pragma unroll
                for (int j = 0; j < 4; ++j)
                    mma_tf32(acc[i][j], aF[i][0], aF[i][1], aF[i][2], aF[i][3],
                             bF[j][0], bF[j][1]);
        }
    }
}

// accumulator element (i,j,e): row = m0 + wm*64 + i*16 + (l>>2) + (e>=2?8:0)
//                              col = n0 + wn*32 + j*8  + (l&3)*2 + (e&1)

__device__ __forceinline__ float silu_f(float v) { return v / (1.f + expf(-v)); }

// ---------------- kernels ----------------
__global__ void prep_w_kernel(const float* __restrict__ wu, const float* __restrict__ wq,
                              const float* __restrict__ wk, const float* __restrict__ wv,
                              const float* __restrict__ wo) {
    int i = blockIdx.x * 256 + threadIdx.x;
    g_Wu[i] = rtf(wu[i]);
    g_Wq[i] = rtf(wq[i]);
    g_Wk[i] = rtf(wk[i]);
    g_Wv[i] = rtf(wv[i]);
    g_Wo[i] = rtf(wo[i]);
}

__global__ void ln_kernel(const float* __restrict__ x,
                          const float* __restrict__ gamma,
                          const float* __restrict__ beta) {
    int row = blockIdx.x;
    const float* xr = x + (size_t)row * HDIM;
    float* out = g_x + (size_t)row * HDIM;

    float s = 0.f, s2 = 0.f;
    for (int i = threadIdx.x; i < HDIM; i += 256) {
        float v = xr[i];
        s += v; s2 += v * v;
    }
    __shared__ float red0[32], red1[32];
    #pragma unroll
    for (int o = 16; o; o >>= 1) {
        s  += __shfl_down_sync(0xffffffffu, s,  o);
        s2 += __shfl_down_sync(0xffffffffu, s2, o);
    }
    int w = threadIdx.x >> 5, l = threadIdx.x & 31;
    if (l == 0) { red0[w] = s; red1[w] = s2; }
    __syncthreads();
    if (threadIdx.x < 32) {
        s  = (l < 8) ? red0[l] : 0.f;
        s2 = (l < 8) ? red1[l] : 0.f;
        #pragma unroll
        for (int o = 4; o; o >>= 1) {
            s  += __shfl_down_sync(0xffffffffu, s,  o);
            s2 += __shfl_down_sync(0xffffffffu, s2, o);
        }
        if (l == 0) { red0[0] = s; red1[0] = s2; }
    }
    __syncthreads();
    float mu  = red0[0] * (1.f / HDIM);
    float var = red1[0] * (1.f / HDIM) - mu * mu;
    float inv = rsqrtf(var + 1e-5f);
    for (int i = threadIdx.x; i < HDIM; i += 256) {
        out[i] = rtf((xr[i] - mu) * inv * gamma[i] + beta[i]);
    }
}

// ---------------- projections: {U,Q,K,V} = silu(x @ W^T + b) ----------------
// z=0: U (full fp32, elementwise operand only)
// z=1,2: Q,K (tf32-rounded, GEMM operands)
// z=3: V -> written TRANSPOSED + rounded into g_Vt
__global__ void __launch_bounds__(256, 2) proj_kernel(
        const float* __restrict__ bu, const float* __restrict__ bq,
        const float* __restrict__ bk, const float* __restrict__ bv) {
    const float* W; const float* bias; float* C;
    switch (blockIdx.z) {
        case 0:  W = g_Wu; bias = bu; C = g_U; break;
        case 1:  W = g_Wq; bias = bq; C = g_Q; break;
        case 2:  W = g_Wk; bias = bk; C = g_K; break;
        default: W = g_Wv; bias = bv; C = nullptr; break;
    }
    int m0 = blockIdx.y * 128, n0 = blockIdx.x * 128;
    float acc[4][4][4] = {};
    gemm_core(g_x + (size_t)m0 * HDIM, HDIM, W + (size_t)n0 * HDIM, HDIM, HDIM, acc);

    int tid = threadIdx.x, l = tid & 31, wid = tid >> 5;
    int wm = wid & 1, wn = wid >> 1, g = l >> 2, tg = l & 3;
    if (blockIdx.z == 3) {
        // transposed store: g_Vt[b][d][t]
        int bb = m0 >> 11;                 // batch (TSEQ = 2048)
        float* Tb = g_Vt + (size_t)bb * HDIM * TSEQ;
        #pragma unroll
        for (int i = 0; i < 4; ++i) {
            int r = m0 + wm * 64 + i * 16 + g;
            int t = r & (TSEQ - 1);
            #pragma unroll
            for (int j = 0; j < 4; ++j) {
                int c = n0 + wn * 32 + j * 8 + tg * 2;
                float2 b2 = *(const float2*)&bias[c];
                Tb[(size_t)c       * TSEQ + t]     = rtf(silu_f(acc[i][j][0] + b2.x));
                Tb[(size_t)(c + 1) * TSEQ + t]     = rtf(silu_f(acc[i][j][1] + b2.y));
                Tb[(size_t)c       * TSEQ + t + 8] = rtf(silu_f(acc[i][j][2] + b2.x));
                Tb[(size_t)(c + 1) * TSEQ + t + 8] = rtf(silu_f(acc[i][j][3] + b2.y));
            }
        }
    } else {
        bool doRound = (blockIdx.z != 0);
        #pragma unroll
        for (int i = 0; i < 4; ++i) {
            int r = m0 + wm * 64 + i * 16 + g;
            #pragma unroll
            for (int j = 0; j < 4; ++j) {
                int c = n0 + wn * 32 + j * 8 + tg * 2;
                float2 b2 = *(const float2*)&bias[c];
                float o0 = silu_f(acc[i][j][0] + b2.x);
                float o1 = silu_f(acc[i][j][1] + b2.y);
                float o2 = silu_f(acc[i][j][2] + b2.x);
                float o3 = silu_f(acc[i][j][3] + b2.y);
                if (doRound) { o0 = rtf(o0); o1 = rtf(o1); o2 = rtf(o2); o3 = rtf(o3); }
                *(float2*)&C[(size_t)r * HDIM + c]       = make_float2(o0, o1);
                *(float2*)&C[(size_t)(r + 8) * HDIM + c] = make_float2(o2, o3);
            }
        }
    }
}

// ---------------- sim: A = relu(Q K^T / sqrt(T))^2, tf32-rounded ----------------
__global__ void __launch_bounds__(256, 2) sim_kernel() {
    int b = blockIdx.z;
    int m0 = blockIdx.y * 128, n0 = blockIdx.x * 128;
    const float* Qb = g_Q + (size_t)b * TSEQ * HDIM;
    const float* Kb = g_K + (size_t)b * TSEQ * HDIM;
    float* C = g_A + (size_t)b * TSEQ * TSEQ;
    float acc[4][4][4] = {};
    gemm_core(Qb + (size_t)m0 * HDIM, HDIM, Kb + (size_t)n0 * HDIM, HDIM, HDIM, acc);

    const float scale = 0.022097086912079608f;  // 1/sqrt(2048)
    int tid = threadIdx.x, l = tid & 31, wid = tid >> 5;
    int wm = wid & 1, wn = wid >> 1, g = l >> 2, tg = l & 3;
    #pragma unroll
    for (int i = 0; i < 4; ++i) {
        int r = m0 + wm * 64 + i * 16 + g;
        #pragma unroll
        for (int j = 0; j < 4; ++j) {
            int c = n0 + wn * 32 + j * 8 + tg * 2;
            float v0 = fmaxf(acc[i][j][0] * scale, 0.f);
            float v1 = fmaxf(acc[i][j][1] * scale, 0.f);
            float v2 = fmaxf(acc[i][j][2] * scale, 0.f);
            float v3 = fmaxf(acc[i][j][3] * scale, 0.f);
            *(float2*)&C[(size_t)r * TSEQ + c]       = make_float2(rtf(v0 * v0), rtf(v1 * v1));
            *(float2*)&C[(size_t)(r + 8) * TSEQ + c] = make_float2(rtf(v2 * v2), rtf(v3 * v3));
        }
    }
}

// ---------------- AV: W = rtf(U * (A @ V)) ----------------
__global__ void __launch_bounds__(256, 2) av_kernel() {
    int b = blockIdx.z;
    int m0 = blockIdx.y * 128, n0 = blockIdx.x * 128;
    const float* Ab = g_A  + (size_t)b * TSEQ * TSEQ;
    const float* Vt = g_Vt + (size_t)b * HDIM * TSEQ;
    const float* Ub = g_U  + (size_t)b * TSEQ * HDIM;
    float* C = g_W + (size_t)b * TSEQ * HDIM;
    float acc[4][4][4] = {};
    gemm_core(Ab + (size_t)m0 * TSEQ, TSEQ, Vt + (size_t)n0 * TSEQ, TSEQ, TSEQ, acc);

    int tid = threadIdx.x, l = tid & 31, wid = tid >> 5;
    int wm = wid & 1, wn = wid >> 1, g = l >> 2, tg = l & 3;
    #pragma unroll
    for (int i = 0; i < 4; ++i) {
        int r = m0 + wm * 64 + i * 16 + g;
        #pragma unroll
        for (int j = 0; j < 4; ++j) {
            int c = n0 + wn * 32 + j * 8 + tg * 2;
            float2 u0 = *(const float2*)&Ub[(size_t)r * HDIM + c];
            float2 u1 = *(const float2*)&Ub[(size_t)(r + 8) * HDIM + c];
            *(float2*)&C[(size_t)r * HDIM + c] =
                make_float2(rtf(acc[i][j][0] * u0.x), rtf(acc[i][j][1] * u0.y));
            *(float2*)&C[(size_t)(r + 8) * HDIM + c] =
                make_float2(rtf(acc[i][j][2] * u1.x), rtf(acc[i][j][3] * u1.y));
        }
    }
}

// ---------------- final: out = W @ Wo^T + bo ----------------
__global__ void __launch_bounds__(256, 2) fin_kernel(const float* __restrict__ bo,
                                                     float* __restrict__ out) {
    int m0 = blockIdx.y * 128, n0 = blockIdx.x * 128;
    float acc[4][4][4] = {};
    gemm_core(g_W + (size_t)m0 * HDIM, HDIM, g_Wo + (size_t)n0 * HDIM, HDIM, HDIM, acc);

    int tid = threadIdx.x, l = tid & 31, wid = tid >> 5;
    int wm = wid & 1, wn = wid >> 1, g = l >> 2, tg = l & 3;
    #pragma unroll
    for (int i = 0; i < 4; ++i) {
        int r = m0 + wm * 64 + i * 16 + g;
        #pragma unroll
        for (int j = 0; j < 4; ++j) {
            int c = n0 + wn * 32 + j * 8 + tg * 2;
            float2 bb = *(const float2*)&bo[c];
            *(float2*)&out[(size_t)r * HDIM + c] =
                make_float2(acc[i][j][0] + bb.x, acc[i][j][1] + bb.y);
            *(float2*)&out[(size_t)(r + 8) * HDIM + c] =
                make_float2(acc[i][j][2] + bb.x, acc[i][j][3] + bb.y);
        }
    }
}

// ---------------- launch ----------------
extern "C" void kernel_launch(void* const* d_in, const int* in_sizes, int n_in,
                              void* d_out, int out_size) {
    const float* hs    = (const float*)d_in[0];
    const float* gamma = (const float*)d_in[1];
    const float* beta  = (const float*)d_in[2];
    const float* Wu    = (const float*)d_in[3];
    const float* bu    = (const float*)d_in[4];
    const float* Wq    = (const float*)d_in[5];
    const float* bq    = (const float*)d_in[6];
    const float* Wk    = (const float*)d_in[7];
    const float* bk    = (const float*)d_in[8];
    const float* Wv    = (const float*)d_in[9];
    const float* bv    = (const float*)d_in[10];
    const float* Wo    = (const float*)d_in[11];
    const float* bo    = (const float*)d_in[12];
    float* out = (float*)d_out;

    cudaFuncSetAttribute(proj_kernel, cudaFuncAttributeMaxDynamicSharedMemorySize, SMEM_BYTES);
    cudaFuncSetAttribute(sim_kernel,  cudaFuncAttributeMaxDynamicSharedMemorySize, SMEM_BYTES);
    cudaFuncSetAttribute(av_kernel,   cudaFuncAttributeMaxDynamicSharedMemorySize, SMEM_BYTES);
    cudaFuncSetAttribute(fin_kernel,  cudaFuncAttributeMaxDynamicSharedMemorySize, SMEM_BYTES);

    prep_w_kernel<<<HDIM * HDIM / 256, 256>>>(Wu, Wq, Wk, Wv, Wo);
    ln_kernel<<<MT, 256>>>(hs, gamma, beta);

    dim3 gp(HDIM / 128, MT / 128, 4);                 // (6, 64, 4)
    proj_kernel<<<gp, 256, SMEM_BYTES>>>(bu, bq, bk, bv);

    dim3 gs(TSEQ / 128, TSEQ / 128, BATCH);           // (16, 16, 4)
    sim_kernel<<<gs, 256, SMEM_BYTES>>>();

    dim3 ga(HDIM / 128, TSEQ / 128, BATCH);           // (6, 16, 4)
    av_kernel<<<ga, 256, SMEM_BYTES>>>();

    dim3 gf(HDIM / 128, MT / 128, 1);                 // (6, 64)
    fin_kernel<<<gf, 256, SMEM_BYTES>>>(bo, out);
}

// round 7
// speedup vs baseline: 5.2596x; 1.6141x over previous
#include <cuda_runtime.h>
#include <cuda_fp16.h>
#include <cstdint>
#include <cmath>

#define HDIM 768
#define TSEQ 2048
#define BATCH 4
#define MT (BATCH * TSEQ)   // 8192

// ---------------- scratch (fp16 GEMM operands) ----------------
__device__ __align__(128) __half g_x [MT * HDIM];
__device__ __align__(128) __half g_U [MT * HDIM];
__device__ __align__(128) __half g_Q [MT * HDIM];
__device__ __align__(128) __half g_K [MT * HDIM];
__device__ __align__(128) __half g_Vt[MT * HDIM];                  // V^T per batch: [d][t]
__device__ __align__(128) __half g_A [(size_t)BATCH * TSEQ * TSEQ];
__device__ __align__(128) __half g_W [MT * HDIM];                  // U * (A @ V)
// fp16 weights
__device__ __align__(128) __half g_Wu[HDIM * HDIM];
__device__ __align__(128) __half g_Wq[HDIM * HDIM];
__device__ __align__(128) __half g_Wk[HDIM * HDIM];
__device__ __align__(128) __half g_Wv[HDIM * HDIM];
__device__ __align__(128) __half g_Wo[HDIM * HDIM];

// ---------------- PTX helpers ----------------
__device__ __forceinline__ uint32_t smem_u32(const void* p) {
    return (uint32_t)__cvta_generic_to_shared(p);
}
__device__ __forceinline__ void cp16(uint32_t dst, const __half* src) {
    asm volatile("cp.async.cg.shared.global [%0], [%1], 16;\n" :: "r"(dst), "l"(src));
}
__device__ __forceinline__ void cp_commit() { asm volatile("cp.async.commit_group;\n"); }
__device__ __forceinline__ void ldsm4(uint32_t addr, uint32_t& r0, uint32_t& r1,
                                      uint32_t& r2, uint32_t& r3) {
    asm volatile("ldmatrix.sync.aligned.m8n8.x4.shared.b16 {%0,%1,%2,%3}, [%4];\n"
                 : "=r"(r0), "=r"(r1), "=r"(r2), "=r"(r3) : "r"(addr));
}
__device__ __forceinline__ void mma_fp16(float c[4],
                                         uint32_t a0, uint32_t a1, uint32_t a2, uint32_t a3,
                                         uint32_t b0, uint32_t b1) {
    asm volatile("mma.sync.aligned.m16n8k16.row.col.f32.f16.f16.f32 "
                 "{%0,%1,%2,%3}, {%4,%5,%6,%7}, {%8,%9}, {%0,%1,%2,%3};\n"
                 : "+f"(c[0]), "+f"(c[1]), "+f"(c[2]), "+f"(c[3])
                 : "r"(a0), "r"(a1), "r"(a2), "r"(a3), "r"(b0), "r"(b1));
}

// ---------------- GEMM core ----------------
// Block: 256 thr = 8 warps. Block tile 128(M) x 128(N), KT=32 (2 x k16), 4-stage cp.async.
// Warp tile 64x32: wm = wid&1, wn = wid>>1.
// smem per stage: A 128x40 halves + B 128x40 halves (stride 40 -> conflict-free ldmatrix).
#define STAGE_HALVES 10240            // A 5120 + B 5120
#define NSTAGE 4
#define SMEM_BYTES   (NSTAGE * STAGE_HALVES * 2)   // 81920

__device__ __forceinline__ void copy_stage(__half* base, const __half* Ag, int lda,
                                           const __half* Bg, int ldb, int k0, int tid) {
    __half* sA = base;
    __half* sB = base + 5120;
    int r  = tid >> 1;                 // 0..127
    int c0 = (tid & 1) * 2;            // chunks {0,1} or {2,3}
    #pragma unroll
    for (int q = 0; q < 2; ++q) {
        int c = c0 + q;                // chunk 0..3 (8 halves each)
        cp16(smem_u32(sA + r * 40 + c * 8), Ag + (size_t)r * lda + k0 + c * 8);
        cp16(smem_u32(sB + r * 40 + c * 8), Bg + (size_t)r * ldb + k0 + c * 8);
    }
}

__device__ __forceinline__ void gemm_core(const __half* Ag, int lda,
                                          const __half* Bg, int ldb,
                                          int K, float acc[4][4][4]) {
    extern __shared__ __half smem[];
    int tid = threadIdx.x;
    int l   = tid & 31;
    int wid = tid >> 5;
    int wm  = wid & 1;
    int wn  = wid >> 1;

    // ldmatrix byte offsets (element = 2B, row stride 40 halves = 80B)
    uint32_t aOff = ((uint32_t)(wm * 64 + (l & 15)) * 40 + (l >> 4) * 8) * 2;
    uint32_t bOff = ((uint32_t)(wn * 32 + (l & 7) + ((l & 16) >> 1)) * 40 + ((l >> 3) & 1) * 8) * 2;

    int nk = K >> 5;   // K multiple of 32, nk >= 3
    copy_stage(smem,                    Ag, lda, Bg, ldb, 0,  tid); cp_commit();
    copy_stage(smem + STAGE_HALVES,     Ag, lda, Bg, ldb, 32, tid); cp_commit();
    copy_stage(smem + 2 * STAGE_HALVES, Ag, lda, Bg, ldb, 64, tid); cp_commit();

    for (int t = 0; t < nk; ++t) {
        asm volatile("cp.async.wait_group 2;\n" ::: "memory");
        __syncthreads();
        int tn = t + 3;
        if (tn < nk) {
            copy_stage(smem + (tn & 3) * STAGE_HALVES, Ag, lda, Bg, ldb, tn * 32, tid);
        }
        cp_commit();

        uint32_t sAu = smem_u32(smem + (t & 3) * STAGE_HALVES);
        uint32_t sBu = sAu + 5120 * 2;
        #pragma unroll
        for (int kk = 0; kk < 2; ++kk) {    // two k16 steps per KT=32
            uint32_t aF[4][4], bF[4][2];
            ldsm4(sBu + bOff +        kk * 32, bF[0][0], bF[0][1], bF[1][0], bF[1][1]);
            ldsm4(sBu + bOff + 1280 + kk * 32, bF[2][0], bF[2][1], bF[3][0], bF[3][1]);
            #pragma unroll
            for (int i = 0; i < 4; ++i)
                ldsm4(sAu + aOff + i * 1280 + kk * 32,
                      aF[i][0], aF[i][1], aF[i][2], aF[i][3]);
            #pragma unroll
            for (int i = 0; i < 4; ++i)
                #pragma unroll
                for (int j = 0; j < 4; ++j)
                    mma_fp16(acc[i][j], aF[i][0], aF[i][1], aF[i][2], aF[i][3],
                             bF[j][0], bF[j][1]);
        }
    }
}

// accumulator element (i,j,e): row = m0 + wm*64 + i*16 + (l>>2) + (e>=2?8:0)
//                              col = n0 + wn*32 + j*8  + (l&3)*2 + (e&1)

__device__ __forceinline__ float silu_f(float v) { return v / (1.f + expf(-v)); }
__device__ __forceinline__ __half2 h2(float a, float b) {
    return __floats2half2_rn(a, b);
}

// ---------------- kernels ----------------
__global__ void prep_w_kernel(const float* __restrict__ wu, const float* __restrict__ wq,
                              const float* __restrict__ wk, const float* __restrict__ wv,
                              const float* __restrict__ wo) {
    int i = blockIdx.x * 256 + threadIdx.x;
    g_Wu[i] = __float2half_rn(wu[i]);
    g_Wq[i] = __float2half_rn(wq[i]);
    g_Wk[i] = __float2half_rn(wk[i]);
    g_Wv[i] = __float2half_rn(wv[i]);
    g_Wo[i] = __float2half_rn(wo[i]);
}

__global__ void ln_kernel(const float* __restrict__ x,
                          const float* __restrict__ gamma,
                          const float* __restrict__ beta) {
    int row = blockIdx.x;
    const float* xr = x + (size_t)row * HDIM;
    __half* out = g_x + (size_t)row * HDIM;

    float s = 0.f, s2 = 0.f;
    for (int i = threadIdx.x; i < HDIM; i += 256) {
        float v = xr[i];
        s += v; s2 += v * v;
    }
    __shared__ float red0[32], red1[32];
    #pragma unroll
    for (int o = 16; o; o >>= 1) {
        s  += __shfl_down_sync(0xffffffffu, s,  o);
        s2 += __shfl_down_sync(0xffffffffu, s2, o);
    }
    int w = threadIdx.x >> 5, l = threadIdx.x & 31;
    if (l == 0) { red0[w] = s; red1[w] = s2; }
    __syncthreads();
    if (threadIdx.x < 32) {
        s  = (l < 8) ? red0[l] : 0.f;
        s2 = (l < 8) ? red1[l] : 0.f;
        #pragma unroll
        for (int o = 4; o; o >>= 1) {
            s  += __shfl_down_sync(0xffffffffu, s,  o);
            s2 += __shfl_down_sync(0xffffffffu, s2, o);
        }
        if (l == 0) { red0[0] = s; red1[0] = s2; }
    }
    __syncthreads();
    float mu  = red0[0] * (1.f / HDIM);
    float var = red1[0] * (1.f / HDIM) - mu * mu;
    float inv = rsqrtf(var + 1e-5f);
    for (int i = threadIdx.x; i < HDIM; i += 256) {
        out[i] = __float2half_rn((xr[i] - mu) * inv * gamma[i] + beta[i]);
    }
}

// ---------------- projections: {U,Q,K,V} = silu(x @ W^T + b) ----------------
// z=0: U, z=1: Q, z=2: K, z=3: V -> written TRANSPOSED into g_Vt
__global__ void __launch_bounds__(256, 2) proj_kernel(
        const float* __restrict__ bu, const float* __restrict__ bq,
        const float* __restrict__ bk, const float* __restrict__ bv) {
    const __half* W; const float* bias;
    switch (blockIdx.z) {
        case 0:  W = g_Wu; bias = bu; break;
        case 1:  W = g_Wq; bias = bq; break;
        case 2:  W = g_Wk; bias = bk; break;
        default: W = g_Wv; bias = bv; break;
    }
    int m0 = blockIdx.y * 128, n0 = blockIdx.x * 128;
    float acc[4][4][4] = {};
    gemm_core(g_x + (size_t)m0 * HDIM, HDIM, W + (size_t)n0 * HDIM, HDIM, HDIM, acc);

    int tid = threadIdx.x, l = tid & 31, wid = tid >> 5;
    int wm = wid & 1, wn = wid >> 1, g = l >> 2, tg = l & 3;
    if (blockIdx.z == 3) {
        int bb = m0 >> 11;
        __half* Tb = g_Vt + (size_t)bb * HDIM * TSEQ;
        #pragma unroll
        for (int i = 0; i < 4; ++i) {
            int r = m0 + wm * 64 + i * 16 + g;
            int t = r & (TSEQ - 1);
            #pragma unroll
            for (int j = 0; j < 4; ++j) {
                int c = n0 + wn * 32 + j * 8 + tg * 2;
                float2 b2 = *(const float2*)&bias[c];
                Tb[(size_t)c       * TSEQ + t]     = __float2half_rn(silu_f(acc[i][j][0] + b2.x));
                Tb[(size_t)(c + 1) * TSEQ + t]     = __float2half_rn(silu_f(acc[i][j][1] + b2.y));
                Tb[(size_t)c       * TSEQ + t + 8] = __float2half_rn(silu_f(acc[i][j][2] + b2.x));
                Tb[(size_t)(c + 1) * TSEQ + t + 8] = __float2half_rn(silu_f(acc[i][j][3] + b2.y));
            }
        }
    } else {
        __half* C = (blockIdx.z == 0) ? g_U : (blockIdx.z == 1 ? g_Q : g_K);
        #pragma unroll
        for (int i = 0; i < 4; ++i) {
            int r = m0 + wm * 64 + i * 16 + g;
            #pragma unroll
            for (int j = 0; j < 4; ++j) {
                int c = n0 + wn * 32 + j * 8 + tg * 2;
                float2 b2 = *(const float2*)&bias[c];
                *(__half2*)&C[(size_t)r * HDIM + c] =
                    h2(silu_f(acc[i][j][0] + b2.x), silu_f(acc[i][j][1] + b2.y));
                *(__half2*)&C[(size_t)(r + 8) * HDIM + c] =
                    h2(silu_f(acc[i][j][2] + b2.x), silu_f(acc[i][j][3] + b2.y));
            }
        }
    }
}

// ---------------- sim: A = relu(Q K^T / sqrt(T))^2 ----------------
__global__ void __launch_bounds__(256, 2) sim_kernel() {
    int b = blockIdx.z;
    int m0 = blockIdx.y * 128, n0 = blockIdx.x * 128;
    const __half* Qb = g_Q + (size_t)b * TSEQ * HDIM;
    const __half* Kb = g_K + (size_t)b * TSEQ * HDIM;
    __half* C = g_A + (size_t)b * TSEQ * TSEQ;
    float acc[4][4][4] = {};
    gemm_core(Qb + (size_t)m0 * HDIM, HDIM, Kb + (size_t)n0 * HDIM, HDIM, HDIM, acc);

    const float scale = 0.022097086912079608f;  // 1/sqrt(2048)
    int tid = threadIdx.x, l = tid & 31, wid = tid >> 5;
    int wm = wid & 1, wn = wid >> 1, g = l >> 2, tg = l & 3;
    #pragma unroll
    for (int i = 0; i < 4; ++i) {
        int r = m0 + wm * 64 + i * 16 + g;
        #pragma unroll
        for (int j = 0; j < 4; ++j) {
            int c = n0 + wn * 32 + j * 8 + tg * 2;
            float v0 = fmaxf(acc[i][j][0] * scale, 0.f);
            float v1 = fmaxf(acc[i][j][1] * scale, 0.f);
            float v2 = fmaxf(acc[i][j][2] * scale, 0.f);
            float v3 = fmaxf(acc[i][j][3] * scale, 0.f);
            *(__half2*)&C[(size_t)r * TSEQ + c]       = h2(v0 * v0, v1 * v1);
            *(__half2*)&C[(size_t)(r + 8) * TSEQ + c] = h2(v2 * v2, v3 * v3);
        }
    }
}

// ---------------- AV: W = U * (A @ V) ----------------
__global__ void __launch_bounds__(256, 2) av_kernel() {
    int b = blockIdx.z;
    int m0 = blockIdx.y * 128, n0 = blockIdx.x * 128;
    const __half* Ab = g_A  + (size_t)b * TSEQ * TSEQ;
    const __half* Vt = g_Vt + (size_t)b * HDIM * TSEQ;
    const __half* Ub = g_U  + (size_t)b * TSEQ * HDIM;
    __half* C = g_W + (size_t)b * TSEQ * HDIM;
    float acc[4][4][4] = {};
    gemm_core(Ab + (size_t)m0 * TSEQ, TSEQ, Vt + (size_t)n0 * TSEQ, TSEQ, TSEQ, acc);

    int tid = threadIdx.x, l = tid & 31, wid = tid >> 5;
    int wm = wid & 1, wn = wid >> 1, g = l >> 2, tg = l & 3;
    #pragma unroll
    for (int i = 0; i < 4; ++i) {
        int r = m0 + wm * 64 + i * 16 + g;
        #pragma unroll
        for (int j = 0; j < 4; ++j) {
            int c = n0 + wn * 32 + j * 8 + tg * 2;
            float2 u0 = __half22float2(*(const __half2*)&Ub[(size_t)r * HDIM + c]);
            float2 u1 = __half22float2(*(const __half2*)&Ub[(size_t)(r + 8) * HDIM + c]);
            *(__half2*)&C[(size_t)r * HDIM + c] =
                h2(acc[i][j][0] * u0.x, acc[i][j][1] * u0.y);
            *(__half2*)&C[(size_t)(r + 8) * HDIM + c] =
                h2(acc[i][j][2] * u1.x, acc[i][j][3] * u1.y);
        }
    }
}

// ---------------- final: out = W @ Wo^T + bo (fp32 out) ----------------
__global__ void __launch_bounds__(256, 2) fin_kernel(const float* __restrict__ bo,
                                                     float* __restrict__ out) {
    int m0 = blockIdx.y * 128, n0 = blockIdx.x * 128;
    float acc[4][4][4] = {};
    gemm_core(g_W + (size_t)m0 * HDIM, HDIM, g_Wo + (size_t)n0 * HDIM, HDIM, HDIM, acc);

    int tid = threadIdx.x, l = tid & 31, wid = tid >> 5;
    int wm = wid & 1, wn = wid >> 1, g = l >> 2, tg = l & 3;
    #pragma unroll
    for (int i = 0; i < 4; ++i) {
        int r = m0 + wm * 64 + i * 16 + g;
        #pragma unroll
        for (int j = 0; j < 4; ++j) {
            int c = n0 + wn * 32 + j * 8 + tg * 2;
            float2 bb = *(const float2*)&bo[c];
            *(float2*)&out[(size_t)r * HDIM + c] =
                make_float2(acc[i][j][0] + bb.x, acc[i][j][1] + bb.y);
            *(float2*)&out[(size_t)(r + 8) * HDIM + c] =
                make_float2(acc[i][j][2] + bb.x, acc[i][j][3] + bb.y);
        }
    }
}

// ---------------- launch ----------------
extern "C" void kernel_launch(void* const* d_in, const int* in_sizes, int n_in,
                              void* d_out, int out_size) {
    const float* hs    = (const float*)d_in[0];
    const float* gamma = (const float*)d_in[1];
    const float* beta  = (const float*)d_in[2];
    const float* Wu    = (const float*)d_in[3];
    const float* bu    = (const float*)d_in[4];
    const float* Wq    = (const float*)d_in[5];
    const float* bq    = (const float*)d_in[6];
    const float* Wk    = (const float*)d_in[7];
    const float* bk    = (const float*)d_in[8];
    const float* Wv    = (const float*)d_in[9];
    const float* bv    = (const float*)d_in[10];
    const float* Wo    = (const float*)d_in[11];
    const float* bo    = (const float*)d_in[12];
    float* out = (float*)d_out;

    cudaFuncSetAttribute(proj_kernel, cudaFuncAttributeMaxDynamicSharedMemorySize, SMEM_BYTES);
    cudaFuncSetAttribute(sim_kernel,  cudaFuncAttributeMaxDynamicSharedMemorySize, SMEM_BYTES);
    cudaFuncSetAttribute(av_kernel,   cudaFuncAttributeMaxDynamicSharedMemorySize, SMEM_BYTES);
    cudaFuncSetAttribute(fin_kernel,  cudaFuncAttributeMaxDynamicSharedMemorySize, SMEM_BYTES);

    prep_w_kernel<<<HDIM * HDIM / 256, 256>>>(Wu, Wq, Wk, Wv, Wo);
    ln_kernel<<<MT, 256>>>(hs, gamma, beta);

    dim3 gp(HDIM / 128, MT / 128, 4);                 // (6, 64, 4)
    proj_kernel<<<gp, 256, SMEM_BYTES>>>(bu, bq, bk, bv);

    dim3 gs(TSEQ / 128, TSEQ / 128, BATCH);           // (16, 16, 4)
    sim_kernel<<<gs, 256, SMEM_BYTES>>>();

    dim3 ga(HDIM / 128, TSEQ / 128, BATCH);           // (6, 16, 4)
    av_kernel<<<ga, 256, SMEM_BYTES>>>();

    dim3 gf(HDIM / 128, MT / 128, 1);                 // (6, 64)
    fin_kernel<<<gf, 256, SMEM_BYTES>>>(bo, out);
}